// round 8
// baseline (speedup 1.0000x reference)
#include <cuda_runtime.h>

__device__ __forceinline__ float frcp(float x){ float y; asm("rcp.approx.ftz.f32 %0,%1;":"=f"(y):"f"(x)); return y; }
__device__ __forceinline__ float fex2(float x){ float y; asm("ex2.approx.ftz.f32 %0,%1;":"=f"(y):"f"(x)); return y; }
__device__ __forceinline__ float flg2(float x){ float y; asm("lg2.approx.ftz.f32 %0,%1;":"=f"(y):"f"(x)); return y; }

#define FM 0xFFFFFFFFu

#define DECL_SLOT(S) float hb##S##0, hd##S##0, hb##S##1, hd##S##1, z##S##0, z##S##1;

// Load row g, horizontal blur 2 px, deposit into window slot S.
#define STEP(S, g) do { \
    const int gg = (g); \
    const bool yin = (unsigned)gg < 1024u; \
    const bool p = yin & colok; \
    const size_t off = (size_t)gg << 10; \
    float bx=0.f, by=0.f, dx=0.f, dy=0.f, zx=0.f, zy=0.f; \
    if (p) { \
        float2 t; \
        t = *(const float2*)(pb + off); bx = t.x; by = t.y; \
        t = *(const float2*)(pd + off); dx = t.x; dy = t.y; \
        t = *(const float2*)(pz + off); zx = t.x; zy = t.y; \
    } \
    const float blx = __shfl_up_sync(FM, bx, 1); \
    const float bly = __shfl_up_sync(FM, by, 1); \
    const float dlx = __shfl_up_sync(FM, dx, 1); \
    const float dly = __shfl_up_sync(FM, dy, 1); \
    const float zlx = __shfl_up_sync(FM, zx, 1); \
    const float zly = __shfl_up_sync(FM, zy, 1); \
    const float brx = __shfl_down_sync(FM, bx, 1); \
    const float bry = __shfl_down_sync(FM, by, 1); \
    const float drx = __shfl_down_sync(FM, dx, 1); \
    const float dry = __shfl_down_sync(FM, dy, 1); \
    const float zrx = __shfl_down_sync(FM, zx, 1); \
    const float zry = __shfl_down_sync(FM, zy, 1); \
    { /* px0: center zx */ \
      const float rz = frcp(zx); \
      float u, a, w; \
      u = fmaf(zlx, rz, -1.f); a = __saturatef(u*u); w = fex2(fmaf(a, c2l, sw0)); \
      float ws = w, bs = w*blx, ds = w*dlx; \
      u = fmaf(zly, rz, -1.f); a = __saturatef(u*u); w = fex2(fmaf(a, c2l, sw1)); \
      ws += w; bs = fmaf(w, bly, bs); ds = fmaf(w, dly, ds); \
      ws += 1.f; bs += bx; ds += dx; /* center tap: w == 1 exactly */ \
      u = fmaf(zy, rz, -1.f); a = __saturatef(u*u); w = fex2(fmaf(a, c2l, sw1)); \
      ws += w; bs = fmaf(w, by, bs); ds = fmaf(w, dy, ds); \
      u = fmaf(zrx, rz, -1.f); a = __saturatef(u*u); w = fex2(fmaf(a, c2l, sw0)); \
      ws += w; bs = fmaf(w, brx, bs); ds = fmaf(w, drx, ds); \
      const float wi = yin ? frcp(ws) : 0.f; \
      hb##S##0 = bs * wi; hd##S##0 = ds * wi; } \
    { /* px1: center zy */ \
      const float rz = frcp(zy); \
      float u, a, w; \
      u = fmaf(zly, rz, -1.f); a = __saturatef(u*u); w = fex2(fmaf(a, c2l, sw0)); \
      float ws = w, bs = w*bly, ds = w*dly; \
      u = fmaf(zx, rz, -1.f); a = __saturatef(u*u); w = fex2(fmaf(a, c2l, sw1)); \
      ws += w; bs = fmaf(w, bx, bs); ds = fmaf(w, dx, ds); \
      ws += 1.f; bs += by; ds += dy; \
      u = fmaf(zrx, rz, -1.f); a = __saturatef(u*u); w = fex2(fmaf(a, c2l, sw1)); \
      ws += w; bs = fmaf(w, brx, bs); ds = fmaf(w, drx, ds); \
      u = fmaf(zry, rz, -1.f); a = __saturatef(u*u); w = fex2(fmaf(a, c2l, sw0)); \
      ws += w; bs = fmaf(w, bry, bs); ds = fmaf(w, dry, ds); \
      const float wi = yin ? frcp(ws) : 0.f; \
      hb##S##1 = bs * wi; hd##S##1 = ds * wi; } \
    z##S##0 = zx; z##S##1 = zy; \
} while(0)

// Vertical blur + blend + store for output row g; taps S0..S4, center S2.
#define EMIT(S0,S1,S2,S3,S4, g) do { \
    const int gg = (g); \
    const bool yin = (unsigned)gg < 1024u; \
    const size_t off = (size_t)gg << 10; \
    float bcx=0.f, bcy=0.f, dcx=0.f, dcy=0.f; \
    if (yin & colok) { \
        float2 t; \
        t = *(const float2*)(pb + off); bcx = t.x; bcy = t.y; \
        t = *(const float2*)(pd + off); dcx = t.x; dcy = t.y; \
    } \
    float o0, o1; \
    { const float rz = frcp(z##S2##0); \
      float u, a, w; \
      u = fmaf(z##S0##0, rz, -1.f); a = __saturatef(u*u); w = fex2(fmaf(a, c2l, sw0)); \
      float ws = w, bs = w*hb##S0##0, ds = w*hd##S0##0; \
      u = fmaf(z##S1##0, rz, -1.f); a = __saturatef(u*u); w = fex2(fmaf(a, c2l, sw1)); \
      ws += w; bs = fmaf(w, hb##S1##0, bs); ds = fmaf(w, hd##S1##0, ds); \
      ws += 1.f; bs += hb##S2##0; ds += hd##S2##0; \
      u = fmaf(z##S3##0, rz, -1.f); a = __saturatef(u*u); w = fex2(fmaf(a, c2l, sw1)); \
      ws += w; bs = fmaf(w, hb##S3##0, bs); ds = fmaf(w, hd##S3##0, ds); \
      u = fmaf(z##S4##0, rz, -1.f); a = __saturatef(u*u); w = fex2(fmaf(a, c2l, sw0)); \
      ws += w; bs = fmaf(w, hb##S4##0, bs); ds = fmaf(w, hd##S4##0, ds); \
      const float wi = frcp(ws); \
      const float bmean = bs * wi, dmean = ds * wi; \
      const float devb = fex2(de * flg2(fmaxf(fabsf(bcx - bmean), 1e-8f))) * ce; \
      const float devd = fmaxf(fex2(de * flg2(fmaxf(fabsf(dcx - dmean), 1e-8f))), eps); \
      o0 = (devd * bcx + devb * dcx) * frcp(devb + devd); } \
    { const float rz = frcp(z##S2##1); \
      float u, a, w; \
      u = fmaf(z##S0##1, rz, -1.f); a = __saturatef(u*u); w = fex2(fmaf(a, c2l, sw0)); \
      float ws = w, bs = w*hb##S0##1, ds = w*hd##S0##1; \
      u = fmaf(z##S1##1, rz, -1.f); a = __saturatef(u*u); w = fex2(fmaf(a, c2l, sw1)); \
      ws += w; bs = fmaf(w, hb##S1##1, bs); ds = fmaf(w, hd##S1##1, ds); \
      ws += 1.f; bs += hb##S2##1; ds += hd##S2##1; \
      u = fmaf(z##S3##1, rz, -1.f); a = __saturatef(u*u); w = fex2(fmaf(a, c2l, sw1)); \
      ws += w; bs = fmaf(w, hb##S3##1, bs); ds = fmaf(w, hd##S3##1, ds); \
      u = fmaf(z##S4##1, rz, -1.f); a = __saturatef(u*u); w = fex2(fmaf(a, c2l, sw0)); \
      ws += w; bs = fmaf(w, hb##S4##1, bs); ds = fmaf(w, hd##S4##1, ds); \
      const float wi = frcp(ws); \
      const float bmean = bs * wi, dmean = ds * wi; \
      const float devb = fex2(de * flg2(fmaxf(fabsf(bcy - bmean), 1e-8f))) * ce; \
      const float devd = fmaxf(fex2(de * flg2(fmaxf(fabsf(dcy - dmean), 1e-8f))), eps); \
      o1 = (devd * bcy + devb * dcy) * frcp(devb + devd); } \
    if (yin & stcol) { *(float2*)(po + off) = make_float2(o0, o1); } \
} while(0)

__global__ __launch_bounds__(32, 32)
void bilateral_kernel(const float* __restrict__ bright,
                      const float* __restrict__ dark,
                      const float* __restrict__ depths,
                      const float* __restrict__ s_dv,
                      const float* __restrict__ s_sv,
                      const float* __restrict__ s_de,
                      const float* __restrict__ s_eps,
                      const float* __restrict__ s_ce,
                      float* __restrict__ out)
{
    const int lane = threadIdx.x;
    const int ys = blockIdx.y;                 // 0..31, strip of 32 output rows
    const int xs = blockIdx.x;                 // 0..17, strip of 60 output cols
    const int r0 = ys * 32;                    // first output row
    const int gx = xs * 60 - 2 + 2 * lane;     // col of this lane's px0 (even)
    const size_t base = (size_t)blockIdx.z << 20;

    const bool colok = (unsigned)gx < 1024u;   // gx even -> gx+1 in-image too
    const bool stcol = (lane >= 1) & (lane <= 30) & colok;

    const float log2e = 1.44269504f;
    const float c2l = -0.5f * frcp(s_dv[0]) * log2e;
    const float svl = -0.5f * frcp(s_sv[0]) * log2e;
    const float sw0 = 4.f * svl, sw1 = svl;    // spatial exps (base-2); center = 0
    const float de = s_de[0], eps = s_eps[0], ce = s_ce[0];

    const float* pb = bright + base + gx;
    const float* pd = dark   + base + gx;
    const float* pz = depths + base + gx;
    float*       po = out    + base + gx;

    DECL_SLOT(A) DECL_SLOT(B) DECL_SLOT(C) DECL_SLOT(D) DECL_SLOT(E)

    // prologue: fill window with rows r0-2 .. r0+1
    STEP(A, r0 - 2);
    STEP(B, r0 - 1);
    STEP(C, r0    );
    STEP(D, r0 + 1);

    // 6 full rotations -> 30 output rows
    #pragma unroll 1
    for (int it = 0; it < 6; it++) {
        const int g = r0 + it * 5;
        STEP(E, g + 2); EMIT(A, B, C, D, E, g    );
        STEP(A, g + 3); EMIT(B, C, D, E, A, g + 1);
        STEP(B, g + 4); EMIT(C, D, E, A, B, g + 2);
        STEP(C, g + 5); EMIT(D, E, A, B, C, g + 3);
        STEP(D, g + 6); EMIT(E, A, B, C, D, g + 4);
    }
    // tail: rows r0+30, r0+31 (window state: A=r0+28 B=r0+29 C=r0+30 D=r0+31)
    STEP(E, r0 + 32); EMIT(A, B, C, D, E, r0 + 30);
    STEP(A, r0 + 33); EMIT(B, C, D, E, A, r0 + 31);
}

extern "C" void kernel_launch(void* const* d_in, const int* in_sizes, int n_in,
                              void* d_out, int out_size)
{
    const float* bright = (const float*)d_in[0];
    const float* dark   = (const float*)d_in[1];
    const float* depths = (const float*)d_in[2];
    const float* s_dv   = (const float*)d_in[3];
    const float* s_sv   = (const float*)d_in[4];
    const float* s_de   = (const float*)d_in[5];
    const float* s_eps  = (const float*)d_in[6];
    const float* s_ce   = (const float*)d_in[7];
    float* out = (float*)d_out;

    const int B = in_sizes[0] / (1024 * 1024);
    // 18 x-strips of 60 cols, 32 y-strips of 32 rows: 4608 CTAs = ONE wave
    // (capacity 148 SM x 32 one-warp CTAs = 4736)
    dim3 grid(18, 32, B);
    bilateral_kernel<<<grid, 32>>>(bright, dark, depths,
                                   s_dv, s_sv, s_de, s_eps, s_ce, out);
}

// round 9
// speedup vs baseline: 1.5193x; 1.5193x over previous
#include <cuda_runtime.h>

__device__ __forceinline__ float frcp(float x){ float y; asm("rcp.approx.ftz.f32 %0,%1;":"=f"(y):"f"(x)); return y; }
__device__ __forceinline__ float fex2(float x){ float y; asm("ex2.approx.ftz.f32 %0,%1;":"=f"(y):"f"(x)); return y; }
__device__ __forceinline__ float flg2(float x){ float y; asm("lg2.approx.ftz.f32 %0,%1;":"=f"(y):"f"(x)); return y; }

#define FM 0xFFFFFFFFu

#define DECL_SLOT(S) float hb##S##0, hd##S##0, hb##S##1, hd##S##1, z##S##0, z##S##1;

// Prefetch one padded row (b,d,z) into pfb/pfd/pfz.
#define LOADROW(g) do { \
    const int gg = (g); \
    const bool p = ((unsigned)gg < 1024u) & colok; \
    const size_t off = (size_t)gg << 10; \
    pfb = p ? *(const float2*)(pb + off) : make_float2(0.f, 0.f); \
    pfd = p ? *(const float2*)(pd + off) : make_float2(0.f, 0.f); \
    pfz = p ? *(const float2*)(pz + off) : make_float2(0.f, 0.f); \
} while(0)

// Prefetch center bright/dark for a future EMIT row into qcb/qcd.
#define LOADCTR(g) do { \
    const int gg = (g); \
    const bool p = ((unsigned)gg < 1024u) & colok; \
    const size_t off = (size_t)gg << 10; \
    qcb = p ? *(const float2*)(pb + off) : make_float2(0.f, 0.f); \
    qcd = p ? *(const float2*)(pd + off) : make_float2(0.f, 0.f); \
} while(0)

// Horizontal blur of prefetched row (pfb/pfd/pfz), deposit into slot S.
#define STEPC(S, g) do { \
    const bool yin = (unsigned)(g) < 1024u; \
    const float bx=pfb.x, by=pfb.y, dx=pfd.x, dy=pfd.y, zx=pfz.x, zy=pfz.y; \
    const float blx = __shfl_up_sync(FM, bx, 1); \
    const float bly = __shfl_up_sync(FM, by, 1); \
    const float dlx = __shfl_up_sync(FM, dx, 1); \
    const float dly = __shfl_up_sync(FM, dy, 1); \
    const float zlx = __shfl_up_sync(FM, zx, 1); \
    const float zly = __shfl_up_sync(FM, zy, 1); \
    const float brx = __shfl_down_sync(FM, bx, 1); \
    const float bry = __shfl_down_sync(FM, by, 1); \
    const float drx = __shfl_down_sync(FM, dx, 1); \
    const float dry = __shfl_down_sync(FM, dy, 1); \
    const float zrx = __shfl_down_sync(FM, zx, 1); \
    const float zry = __shfl_down_sync(FM, zy, 1); \
    { /* px0 */ \
      const float rz = frcp(zx); \
      float u, a, w; \
      u = fmaf(zlx, rz, -1.f); a = __saturatef(u*u); w = fex2(fmaf(a, c2l, sw0)); \
      float ws = w, bs = w*blx, ds = w*dlx; \
      u = fmaf(zly, rz, -1.f); a = __saturatef(u*u); w = fex2(fmaf(a, c2l, sw1)); \
      ws += w; bs = fmaf(w, bly, bs); ds = fmaf(w, dly, ds); \
      ws += 1.f; bs += bx; ds += dx; /* center tap: w == 1 exactly */ \
      u = fmaf(zy, rz, -1.f); a = __saturatef(u*u); w = fex2(fmaf(a, c2l, sw1)); \
      ws += w; bs = fmaf(w, by, bs); ds = fmaf(w, dy, ds); \
      u = fmaf(zrx, rz, -1.f); a = __saturatef(u*u); w = fex2(fmaf(a, c2l, sw0)); \
      ws += w; bs = fmaf(w, brx, bs); ds = fmaf(w, drx, ds); \
      const float wi = yin ? frcp(ws) : 0.f; \
      hb##S##0 = bs * wi; hd##S##0 = ds * wi; } \
    { /* px1 */ \
      const float rz = frcp(zy); \
      float u, a, w; \
      u = fmaf(zly, rz, -1.f); a = __saturatef(u*u); w = fex2(fmaf(a, c2l, sw0)); \
      float ws = w, bs = w*bly, ds = w*dly; \
      u = fmaf(zx, rz, -1.f); a = __saturatef(u*u); w = fex2(fmaf(a, c2l, sw1)); \
      ws += w; bs = fmaf(w, bx, bs); ds = fmaf(w, dx, ds); \
      ws += 1.f; bs += by; ds += dy; \
      u = fmaf(zrx, rz, -1.f); a = __saturatef(u*u); w = fex2(fmaf(a, c2l, sw1)); \
      ws += w; bs = fmaf(w, brx, bs); ds = fmaf(w, drx, ds); \
      u = fmaf(zry, rz, -1.f); a = __saturatef(u*u); w = fex2(fmaf(a, c2l, sw0)); \
      ws += w; bs = fmaf(w, bry, bs); ds = fmaf(w, dry, ds); \
      const float wi = yin ? frcp(ws) : 0.f; \
      hb##S##1 = bs * wi; hd##S##1 = ds * wi; } \
    z##S##0 = zx; z##S##1 = zy; \
} while(0)

// Vertical blur + blend + store for output row g; center b/d from qcb/qcd.
#define EMIT(S0,S1,S2,S3,S4, g) do { \
    const int gg = (g); \
    const bool yin = (unsigned)gg < 1024u; \
    const float bcx=qcb.x, bcy=qcb.y, dcx=qcd.x, dcy=qcd.y; \
    float o0, o1; \
    { const float rz = frcp(z##S2##0); \
      float u, a, w; \
      u = fmaf(z##S0##0, rz, -1.f); a = __saturatef(u*u); w = fex2(fmaf(a, c2l, sw0)); \
      float ws = w, bs = w*hb##S0##0, ds = w*hd##S0##0; \
      u = fmaf(z##S1##0, rz, -1.f); a = __saturatef(u*u); w = fex2(fmaf(a, c2l, sw1)); \
      ws += w; bs = fmaf(w, hb##S1##0, bs); ds = fmaf(w, hd##S1##0, ds); \
      ws += 1.f; bs += hb##S2##0; ds += hd##S2##0; \
      u = fmaf(z##S3##0, rz, -1.f); a = __saturatef(u*u); w = fex2(fmaf(a, c2l, sw1)); \
      ws += w; bs = fmaf(w, hb##S3##0, bs); ds = fmaf(w, hd##S3##0, ds); \
      u = fmaf(z##S4##0, rz, -1.f); a = __saturatef(u*u); w = fex2(fmaf(a, c2l, sw0)); \
      ws += w; bs = fmaf(w, hb##S4##0, bs); ds = fmaf(w, hd##S4##0, ds); \
      const float wi = frcp(ws); \
      const float bmean = bs * wi, dmean = ds * wi; \
      const float devb = fex2(de * flg2(fmaxf(fabsf(bcx - bmean), 1e-8f))) * ce; \
      const float devd = fmaxf(fex2(de * flg2(fmaxf(fabsf(dcx - dmean), 1e-8f))), eps); \
      o0 = (devd * bcx + devb * dcx) * frcp(devb + devd); } \
    { const float rz = frcp(z##S2##1); \
      float u, a, w; \
      u = fmaf(z##S0##1, rz, -1.f); a = __saturatef(u*u); w = fex2(fmaf(a, c2l, sw0)); \
      float ws = w, bs = w*hb##S0##1, ds = w*hd##S0##1; \
      u = fmaf(z##S1##1, rz, -1.f); a = __saturatef(u*u); w = fex2(fmaf(a, c2l, sw1)); \
      ws += w; bs = fmaf(w, hb##S1##1, bs); ds = fmaf(w, hd##S1##1, ds); \
      ws += 1.f; bs += hb##S2##1; ds += hd##S2##1; \
      u = fmaf(z##S3##1, rz, -1.f); a = __saturatef(u*u); w = fex2(fmaf(a, c2l, sw1)); \
      ws += w; bs = fmaf(w, hb##S3##1, bs); ds = fmaf(w, hd##S3##1, ds); \
      u = fmaf(z##S4##1, rz, -1.f); a = __saturatef(u*u); w = fex2(fmaf(a, c2l, sw0)); \
      ws += w; bs = fmaf(w, hb##S4##1, bs); ds = fmaf(w, hd##S4##1, ds); \
      const float wi = frcp(ws); \
      const float bmean = bs * wi, dmean = ds * wi; \
      const float devb = fex2(de * flg2(fmaxf(fabsf(bcy - bmean), 1e-8f))) * ce; \
      const float devd = fmaxf(fex2(de * flg2(fmaxf(fabsf(dcy - dmean), 1e-8f))), eps); \
      o1 = (devd * bcy + devb * dcy) * frcp(devb + devd); } \
    if (yin & stcol) { *(float2*)(po + ((size_t)gg << 10)) = make_float2(o0, o1); } \
} while(0)

__global__ __launch_bounds__(32, 30)
void bilateral_kernel(const float* __restrict__ bright,
                      const float* __restrict__ dark,
                      const float* __restrict__ depths,
                      const float* __restrict__ s_dv,
                      const float* __restrict__ s_sv,
                      const float* __restrict__ s_de,
                      const float* __restrict__ s_eps,
                      const float* __restrict__ s_ce,
                      float* __restrict__ out)
{
    const int lane = threadIdx.x;
    const int ys = blockIdx.y;                 // 0..29, strip of 35 output rows
    const int xs = blockIdx.x;                 // 0..17, strip of 60 output cols
    const int r0 = ys * 35;                    // first output row
    const int gx = xs * 60 - 2 + 2 * lane;     // col of this lane's px0 (even)
    const size_t base = (size_t)blockIdx.z << 20;

    const bool colok = (unsigned)gx < 1024u;   // gx even -> gx+1 in-image too
    const bool stcol = (lane >= 1) & (lane <= 30) & colok;

    const float log2e = 1.44269504f;
    const float c2l = -0.5f * frcp(s_dv[0]) * log2e;
    const float svl = -0.5f * frcp(s_sv[0]) * log2e;
    const float sw0 = 4.f * svl, sw1 = svl;    // spatial exps (base-2); center = 0
    const float de = s_de[0], eps = s_eps[0], ce = s_ce[0];

    const float* pb = bright + base + gx;
    const float* pd = dark   + base + gx;
    const float* pz = depths + base + gx;
    float*       po = out    + base + gx;

    DECL_SLOT(A) DECL_SLOT(B) DECL_SLOT(C) DECL_SLOT(D) DECL_SLOT(E)
    float2 pfb, pfd, pfz;      // prefetched padded row
    float2 qcb, qcd;           // prefetched center b/d for next EMIT row

    // prologue: fill window with rows r0-2 .. r0+1, keep one row in flight
    LOADROW(r0 - 2);
    STEPC(A, r0 - 2); LOADROW(r0 - 1);
    STEPC(B, r0 - 1); LOADROW(r0    );
    STEPC(C, r0    ); LOADROW(r0 + 1); LOADCTR(r0);
    STEPC(D, r0 + 1); LOADROW(r0 + 2);

    // 7 rotations x 5 rows = 35 output rows; every LDG is one STEP+EMIT ahead
    #pragma unroll 1
    for (int it = 0; it < 7; it++) {
        const int g = r0 + it * 5;
        STEPC(E, g + 2); LOADROW(g + 3); EMIT(A, B, C, D, E, g    ); LOADCTR(g + 1);
        STEPC(A, g + 3); LOADROW(g + 4); EMIT(B, C, D, E, A, g + 1); LOADCTR(g + 2);
        STEPC(B, g + 4); LOADROW(g + 5); EMIT(C, D, E, A, B, g + 2); LOADCTR(g + 3);
        STEPC(C, g + 5); LOADROW(g + 6); EMIT(D, E, A, B, C, g + 3); LOADCTR(g + 4);
        STEPC(D, g + 6); LOADROW(g + 7); EMIT(E, A, B, C, D, g + 4); LOADCTR(g + 5);
    }
}

extern "C" void kernel_launch(void* const* d_in, const int* in_sizes, int n_in,
                              void* d_out, int out_size)
{
    const float* bright = (const float*)d_in[0];
    const float* dark   = (const float*)d_in[1];
    const float* depths = (const float*)d_in[2];
    const float* s_dv   = (const float*)d_in[3];
    const float* s_sv   = (const float*)d_in[4];
    const float* s_de   = (const float*)d_in[5];
    const float* s_eps  = (const float*)d_in[6];
    const float* s_ce   = (const float*)d_in[7];
    float* out = (float*)d_out;

    const int B = in_sizes[0] / (1024 * 1024);
    // 18 x-strips of 60 cols, 30 y-strips of 35 rows: 4320 one-warp CTAs
    // (single wave at 30 CTAs/SM, launch_bounds(32,30) -> <=68 regs)
    dim3 grid(18, 30, B);
    bilateral_kernel<<<grid, 32>>>(bright, dark, depths,
                                   s_dv, s_sv, s_de, s_eps, s_ce, out);
}

// round 10
// speedup vs baseline: 1.5360x; 1.0110x over previous
#include <cuda_runtime.h>

__device__ __forceinline__ float frcp(float x){ float y; asm("rcp.approx.ftz.f32 %0,%1;":"=f"(y):"f"(x)); return y; }
__device__ __forceinline__ float fex2(float x){ float y; asm("ex2.approx.ftz.f32 %0,%1;":"=f"(y):"f"(x)); return y; }
__device__ __forceinline__ float flg2(float x){ float y; asm("lg2.approx.ftz.f32 %0,%1;":"=f"(y):"f"(x)); return y; }

#define FM 0xFFFFFFFFu

#define DECL_SLOT(S) float hb##S##0, hd##S##0, hb##S##1, hd##S##1, z##S##0, z##S##1;

// Prefetch one padded row (b,d,z) into pfb/pfd/pfz.
#define LOADROW(g) do { \
    const int gg = (g); \
    const bool p = ((unsigned)gg < 1024u) & colok; \
    const size_t off = (size_t)gg << 10; \
    pfb = p ? *(const float2*)(pb + off) : make_float2(0.f, 0.f); \
    pfd = p ? *(const float2*)(pd + off) : make_float2(0.f, 0.f); \
    pfz = p ? *(const float2*)(pz + off) : make_float2(0.f, 0.f); \
} while(0)

// Horizontal blur of prefetched row (pfb/pfd/pfz), deposit into slot S.
#define STEPC(S, g) do { \
    const bool yin = (unsigned)(g) < 1024u; \
    const float bx=pfb.x, by=pfb.y, dx=pfd.x, dy=pfd.y, zx=pfz.x, zy=pfz.y; \
    const float blx = __shfl_up_sync(FM, bx, 1); \
    const float bly = __shfl_up_sync(FM, by, 1); \
    const float dlx = __shfl_up_sync(FM, dx, 1); \
    const float dly = __shfl_up_sync(FM, dy, 1); \
    const float zlx = __shfl_up_sync(FM, zx, 1); \
    const float zly = __shfl_up_sync(FM, zy, 1); \
    const float brx = __shfl_down_sync(FM, bx, 1); \
    const float bry = __shfl_down_sync(FM, by, 1); \
    const float drx = __shfl_down_sync(FM, dx, 1); \
    const float dry = __shfl_down_sync(FM, dy, 1); \
    const float zrx = __shfl_down_sync(FM, zx, 1); \
    const float zry = __shfl_down_sync(FM, zy, 1); \
    { /* px0 */ \
      const float rz = frcp(zx); \
      float u, a, w; \
      u = fmaf(zlx, rz, -1.f); a = __saturatef(u*u); w = fex2(fmaf(a, c2l, sw0)); \
      float ws = w, bs = w*blx, ds = w*dlx; \
      u = fmaf(zly, rz, -1.f); a = __saturatef(u*u); w = fex2(fmaf(a, c2l, sw1)); \
      ws += w; bs = fmaf(w, bly, bs); ds = fmaf(w, dly, ds); \
      ws += 1.f; bs += bx; ds += dx; /* center tap: w == 1 exactly */ \
      u = fmaf(zy, rz, -1.f); a = __saturatef(u*u); w = fex2(fmaf(a, c2l, sw1)); \
      ws += w; bs = fmaf(w, by, bs); ds = fmaf(w, dy, ds); \
      u = fmaf(zrx, rz, -1.f); a = __saturatef(u*u); w = fex2(fmaf(a, c2l, sw0)); \
      ws += w; bs = fmaf(w, brx, bs); ds = fmaf(w, drx, ds); \
      const float wi = yin ? frcp(ws) : 0.f; \
      hb##S##0 = bs * wi; hd##S##0 = ds * wi; } \
    { /* px1 */ \
      const float rz = frcp(zy); \
      float u, a, w; \
      u = fmaf(zly, rz, -1.f); a = __saturatef(u*u); w = fex2(fmaf(a, c2l, sw0)); \
      float ws = w, bs = w*bly, ds = w*dly; \
      u = fmaf(zx, rz, -1.f); a = __saturatef(u*u); w = fex2(fmaf(a, c2l, sw1)); \
      ws += w; bs = fmaf(w, bx, bs); ds = fmaf(w, dx, ds); \
      ws += 1.f; bs += by; ds += dy; \
      u = fmaf(zrx, rz, -1.f); a = __saturatef(u*u); w = fex2(fmaf(a, c2l, sw1)); \
      ws += w; bs = fmaf(w, brx, bs); ds = fmaf(w, drx, ds); \
      u = fmaf(zry, rz, -1.f); a = __saturatef(u*u); w = fex2(fmaf(a, c2l, sw0)); \
      ws += w; bs = fmaf(w, bry, bs); ds = fmaf(w, dry, ds); \
      const float wi = yin ? frcp(ws) : 0.f; \
      hb##S##1 = bs * wi; hd##S##1 = ds * wi; } \
    z##S##0 = zx; z##S##1 = zy; \
} while(0)

// Vertical blur + blend + store for output row g.
// Center b/d loaded here directly: the line was fetched by LOADROW(g) three
// phases earlier, so this is an L1 hit whose latency is covered by the tap math.
#define EMIT(S0,S1,S2,S3,S4, g) do { \
    const int gg = (g); \
    const bool yin = (unsigned)gg < 1024u; \
    const size_t off = (size_t)gg << 10; \
    const bool cp = yin & colok; \
    const float2 cb = cp ? *(const float2*)(pb + off) : make_float2(0.f, 0.f); \
    const float2 cd = cp ? *(const float2*)(pd + off) : make_float2(0.f, 0.f); \
    float o0, o1; \
    { const float rz = frcp(z##S2##0); \
      float u, a, w; \
      u = fmaf(z##S0##0, rz, -1.f); a = __saturatef(u*u); w = fex2(fmaf(a, c2l, sw0)); \
      float ws = w, bs = w*hb##S0##0, ds = w*hd##S0##0; \
      u = fmaf(z##S1##0, rz, -1.f); a = __saturatef(u*u); w = fex2(fmaf(a, c2l, sw1)); \
      ws += w; bs = fmaf(w, hb##S1##0, bs); ds = fmaf(w, hd##S1##0, ds); \
      ws += 1.f; bs += hb##S2##0; ds += hd##S2##0; \
      u = fmaf(z##S3##0, rz, -1.f); a = __saturatef(u*u); w = fex2(fmaf(a, c2l, sw1)); \
      ws += w; bs = fmaf(w, hb##S3##0, bs); ds = fmaf(w, hd##S3##0, ds); \
      u = fmaf(z##S4##0, rz, -1.f); a = __saturatef(u*u); w = fex2(fmaf(a, c2l, sw0)); \
      ws += w; bs = fmaf(w, hb##S4##0, bs); ds = fmaf(w, hd##S4##0, ds); \
      const float wi = frcp(ws); \
      const float bmean = bs * wi, dmean = ds * wi; \
      const float devb = fex2(de * flg2(fmaxf(fabsf(cb.x - bmean), 1e-8f))) * ce; \
      const float devd = fmaxf(fex2(de * flg2(fmaxf(fabsf(cd.x - dmean), 1e-8f))), eps); \
      o0 = (devd * cb.x + devb * cd.x) * frcp(devb + devd); } \
    { const float rz = frcp(z##S2##1); \
      float u, a, w; \
      u = fmaf(z##S0##1, rz, -1.f); a = __saturatef(u*u); w = fex2(fmaf(a, c2l, sw0)); \
      float ws = w, bs = w*hb##S0##1, ds = w*hd##S0##1; \
      u = fmaf(z##S1##1, rz, -1.f); a = __saturatef(u*u); w = fex2(fmaf(a, c2l, sw1)); \
      ws += w; bs = fmaf(w, hb##S1##1, bs); ds = fmaf(w, hd##S1##1, ds); \
      ws += 1.f; bs += hb##S2##1; ds += hd##S2##1; \
      u = fmaf(z##S3##1, rz, -1.f); a = __saturatef(u*u); w = fex2(fmaf(a, c2l, sw1)); \
      ws += w; bs = fmaf(w, hb##S3##1, bs); ds = fmaf(w, hd##S3##1, ds); \
      u = fmaf(z##S4##1, rz, -1.f); a = __saturatef(u*u); w = fex2(fmaf(a, c2l, sw0)); \
      ws += w; bs = fmaf(w, hb##S4##1, bs); ds = fmaf(w, hd##S4##1, ds); \
      const float wi = frcp(ws); \
      const float bmean = bs * wi, dmean = ds * wi; \
      const float devb = fex2(de * flg2(fmaxf(fabsf(cb.y - bmean), 1e-8f))) * ce; \
      const float devd = fmaxf(fex2(de * flg2(fmaxf(fabsf(cd.y - dmean), 1e-8f))), eps); \
      o1 = (devd * cb.y + devb * cd.y) * frcp(devb + devd); } \
    if (yin & stcol) { *(float2*)(po + off) = make_float2(o0, o1); } \
} while(0)

__global__ __launch_bounds__(32, 30)
void bilateral_kernel(const float* __restrict__ bright,
                      const float* __restrict__ dark,
                      const float* __restrict__ depths,
                      const float* __restrict__ s_dv,
                      const float* __restrict__ s_sv,
                      const float* __restrict__ s_de,
                      const float* __restrict__ s_eps,
                      const float* __restrict__ s_ce,
                      float* __restrict__ out)
{
    const int lane = threadIdx.x;
    const int ys = blockIdx.y;                 // 0..29, strip of 35 output rows
    const int xs = blockIdx.x;                 // 0..17, strip of 60 output cols
    const int r0 = ys * 35;                    // first output row
    const int gx = xs * 60 - 2 + 2 * lane;     // col of this lane's px0 (even)
    const size_t base = (size_t)blockIdx.z << 20;

    const bool colok = (unsigned)gx < 1024u;   // gx even -> gx+1 in-image too
    const bool stcol = (lane >= 1) & (lane <= 30) & colok;

    const float log2e = 1.44269504f;
    const float c2l = -0.5f * frcp(s_dv[0]) * log2e;
    const float svl = -0.5f * frcp(s_sv[0]) * log2e;
    const float sw0 = 4.f * svl, sw1 = svl;    // spatial exps (base-2); center = 0
    const float de = s_de[0], eps = s_eps[0], ce = s_ce[0];

    const float* pb = bright + base + gx;
    const float* pd = dark   + base + gx;
    const float* pz = depths + base + gx;
    float*       po = out    + base + gx;

    DECL_SLOT(A) DECL_SLOT(B) DECL_SLOT(C) DECL_SLOT(D) DECL_SLOT(E)
    float2 pfb, pfd, pfz;      // prefetched padded row

    // prologue: fill window with rows r0-2 .. r0+1, keep one row in flight
    LOADROW(r0 - 2);
    STEPC(A, r0 - 2); LOADROW(r0 - 1);
    STEPC(B, r0 - 1); LOADROW(r0    );
    STEPC(C, r0    ); LOADROW(r0 + 1);
    STEPC(D, r0 + 1); LOADROW(r0 + 2);

    // rotations of 5 rows; tail strips stop once past row 1023
    const int nrot = min(7, (1024 - r0 + 4) / 5);
    #pragma unroll 1
    for (int it = 0; it < nrot; it++) {
        const int g = r0 + it * 5;
        STEPC(E, g + 2); LOADROW(g + 3); EMIT(A, B, C, D, E, g    );
        STEPC(A, g + 3); LOADROW(g + 4); EMIT(B, C, D, E, A, g + 1);
        STEPC(B, g + 4); LOADROW(g + 5); EMIT(C, D, E, A, B, g + 2);
        STEPC(C, g + 5); LOADROW(g + 6); EMIT(D, E, A, B, C, g + 3);
        STEPC(D, g + 6); LOADROW(g + 7); EMIT(E, A, B, C, D, g + 4);
    }
}

extern "C" void kernel_launch(void* const* d_in, const int* in_sizes, int n_in,
                              void* d_out, int out_size)
{
    const float* bright = (const float*)d_in[0];
    const float* dark   = (const float*)d_in[1];
    const float* depths = (const float*)d_in[2];
    const float* s_dv   = (const float*)d_in[3];
    const float* s_sv   = (const float*)d_in[4];
    const float* s_de   = (const float*)d_in[5];
    const float* s_eps  = (const float*)d_in[6];
    const float* s_ce   = (const float*)d_in[7];
    float* out = (float*)d_out;

    const int B = in_sizes[0] / (1024 * 1024);
    // 18 x-strips of 60 cols, 30 y-strips of 35 rows: 4320 one-warp CTAs
    // (single wave at 30 CTAs/SM, launch_bounds(32,30) -> <=68 regs)
    dim3 grid(18, 30, B);
    bilateral_kernel<<<grid, 32>>>(bright, dark, depths,
                                   s_dv, s_sv, s_de, s_eps, s_ce, out);
}